// round 12
// baseline (speedup 1.0000x reference)
#include <cuda_runtime.h>
#include <cuda_bf16.h>
#include <cstdint>
#include <math.h>

// ============================================================================
// ScaledDotAttention via mma.sync (HMMA bf16), sm_103-compatible PTX only.
//   out = softmax((Q.Mem^T/sqrt(D)) * W) . Mem     Q=4096, M=8192, D=128 fp32
//
// Round 10 = Round 7 design with the loader bug fixed (rep<8, was rep<16:
// wrote rows 16..31 of a 16-row slice -> gmem OOB cp.async + smem overflow).
//
// Design (vs R6, 157.9 us, tensor=56%, L1=61% binding):
//  - warp = ALL 32 q-rows x PRIVATE 16-row j-slice (8 warps cover 128 j rows):
//      * S-phase B and PV-phase B duplication across warps eliminated
//      * ldsm.x4 per warp per tile: 80 -> 64  (L1 bytes -17%)
//  - fully per-warp cp.async double buffer: NO block/named barriers in the
//    main loop (wait_group + syncwarp only) -> 8 self-paced pipelines/SM
//  - warp accumulates full 32x128 O for its j-slice; single cross-warp smem
//    atomic reduction at the end
// ============================================================================

namespace {
constexpr int QT = 4096, MT = 8192, DD = 128;
constexpr int BQ = 32, BM = 128, TILES = MT / BM;   // 64 tiles
constexpr int THREADS = 256;

// smem layout (bytes)
constexpr int S_QH  = 0;          // Q hi [2 d-halves][32 rows][128B] = 8KB
constexpr int S_QL  = 8192;       // Q lo = 8KB
constexpr int S_M   = 16384;      // 8 warps x 2 stages x 8KB slice = 128KB
constexpr int WSTRIDE = 16384;    // per-warp (2 stages)
constexpr int STG   = 8192;       // stage: hi 4KB + lo 4KB
constexpr int S_LSUM = S_M + 8 * WSTRIDE;   // 147456
constexpr int SMEM_TOTAL = S_LSUM + 512;
}

// preprocessed bf16 hi/lo operands
__device__ __align__(16) __nv_bfloat16 g_q_h[QT * DD];
__device__ __align__(16) __nv_bfloat16 g_q_l[QT * DD];
__device__ __align__(16) __nv_bfloat16 g_m_h[MT * DD];
__device__ __align__(16) __nv_bfloat16 g_m_l[MT * DD];

// ---------------- helpers ----------------
__device__ __forceinline__ uint32_t smem_to_u32(const void* p) {
    uint32_t a;
    asm("{ .reg .u64 t; cvta.to.shared.u64 t, %1; cvt.u32.u64 %0, t; }" : "=r"(a) : "l"(p));
    return a;
}
__device__ __forceinline__ uint32_t sw128(uint32_t o) { return o ^ ((o >> 3) & 0x70); }

__device__ __forceinline__ void ldsm_x4(uint32_t* r, uint32_t a) {
    asm volatile("ldmatrix.sync.aligned.m8n8.x4.shared.b16 {%0,%1,%2,%3}, [%4];"
                 : "=r"(r[0]), "=r"(r[1]), "=r"(r[2]), "=r"(r[3]) : "r"(a));
}
__device__ __forceinline__ void ldsm_x4t(uint32_t* r, uint32_t a) {
    asm volatile("ldmatrix.sync.aligned.m8n8.x4.trans.shared.b16 {%0,%1,%2,%3}, [%4];"
                 : "=r"(r[0]), "=r"(r[1]), "=r"(r[2]), "=r"(r[3]) : "r"(a));
}
__device__ __forceinline__ void mma_bf16(float* c, const uint32_t* a, const uint32_t* b) {
    asm volatile("mma.sync.aligned.m16n8k16.row.col.f32.bf16.bf16.f32 "
                 "{%0,%1,%2,%3}, {%4,%5,%6,%7}, {%8,%9}, {%0,%1,%2,%3};"
                 : "+f"(c[0]), "+f"(c[1]), "+f"(c[2]), "+f"(c[3])
                 : "r"(a[0]), "r"(a[1]), "r"(a[2]), "r"(a[3]), "r"(b[0]), "r"(b[1]));
}
__device__ __forceinline__ uint32_t pack_bf16x2(float lo, float hi) {
    __nv_bfloat162 v = __floats2bfloat162_rn(lo, hi);
    return *reinterpret_cast<uint32_t*>(&v);
}
#define CP_ASYNC16(dst, src) \
    asm volatile("cp.async.cg.shared.global [%0], [%1], 16;" :: "r"(dst), "l"(src))
#define CP_COMMIT() asm volatile("cp.async.commit_group;" ::: "memory")
#define CP_WAIT1()  asm volatile("cp.async.wait_group 1;" ::: "memory")

// ---------------- merged prep kernel ----------------
__global__ void prep_kernel(const float* __restrict__ q, const float* __restrict__ m) {
    int idx = blockIdx.x * blockDim.x + threadIdx.x;
    if (idx < QT * DD) {
        float v = q[idx] * 0.088388347648318440550f;   // 1/sqrt(128)
        __nv_bfloat16 h = __float2bfloat16(v);
        g_q_h[idx] = h;
        g_q_l[idx] = __float2bfloat16(v - __bfloat162float(h));
    }
    int midx = idx - QT * DD;
    if (midx >= 0 && midx < MT * DD) {
        float v = m[midx];
        __nv_bfloat16 h = __float2bfloat16(v);
        g_m_h[midx] = h;
        g_m_l[midx] = __float2bfloat16(v - __bfloat162float(h));
    }
}

// ---------------- main kernel ----------------
__global__ __launch_bounds__(THREADS, 1)
void attn_mma_kernel(const float* __restrict__ weights, float* __restrict__ out)
{
    extern __shared__ char smem[];
    const uint32_t sb = smem_to_u32(smem);
    const int tid  = threadIdx.x;
    const int wid  = tid >> 5;
    const int lane = tid & 31;
    const int gid  = lane >> 2;
    const int tig  = lane & 3;
    const int q0   = blockIdx.x * BQ;
    const int jw   = wid * 16;        // warp's private 16-row j-slice

    float* lsum = (float*)(smem + S_LSUM);
    if (tid < 32) lsum[tid] = 0.f;

    // ---- load Q tile hi/lo (once) ----
    for (int it = tid; it < 32 * 16; it += THREADS) {
        int row = it >> 4, ch = it & 15;
        uint32_t o = sw128((uint32_t)((ch >> 3) * 4096 + row * 128 + (ch & 7) * 16));
        *(uint4*)(smem + S_QH + o) = *(const uint4*)(g_q_h + (size_t)(q0 + row) * DD + ch * 8);
        *(uint4*)(smem + S_QL + o) = *(const uint4*)(g_q_l + (size_t)(q0 + row) * DD + ch * 8);
    }

    // per-lane addressing
    const int rowA   = lane & 15;                 // A(Q): +0 / +16 for the 2 m-frags
    const int selA   = lane >> 4;
    const int sb_row = ((lane >> 4) & 1) * 8 + (lane & 7);   // S-B: 16 slice rows
    const int sb_sel = (lane >> 3) & 1;
    const int pv_row = lane & 15;                 // PV-B: 16 K rows
    const int pv_sel = lane >> 4;

    float o_acc[2][16][4];                        // [m-frag][d-frag][e] = 128 regs
    #pragma unroll
    for (int mf = 0; mf < 2; ++mf)
        #pragma unroll
        for (int nf = 0; nf < 16; ++nf)
            #pragma unroll
            for (int e = 0; e < 4; ++e) o_acc[mf][nf][e] = 0.f;
    float rs[4] = {0.f, 0.f, 0.f, 0.f};           // row sums

    // weights base: rows (q0 + mf*16 + gid [+8]), cols (m0 + jw + nf*8 + tig*2)
    const float* wbase = weights + (size_t)(q0 + gid) * MT + jw + tig * 2;

    // per-warp slice loader: 16 rows x 16 chunks = 256 items = 32 lanes x 8 reps
    const uint32_t wslice = sb + S_M + wid * WSTRIDE;
    auto load_slice = [&](int t, int buf) {
        const int m0 = t * BM + jw;
        const uint32_t base = wslice + buf * STG;
        int it = lane;
        #pragma unroll
        for (int rep = 0; rep < 8; ++rep, it += 32) {   // FIX: 8 reps (was 16)
            int row = it >> 4, ch = it & 15;            // row 0..15, ch 0..15
            uint32_t o = sw128((uint32_t)((ch >> 3) * 2048 + row * 128 + (ch & 7) * 16));
            size_t gs = (size_t)(m0 + row) * DD + ch * 8;
            CP_ASYNC16(base + o,        (const void*)(g_m_h + gs));
            CP_ASYNC16(base + 4096 + o, (const void*)(g_m_l + gs));
        }
    };

    __syncthreads();   // Q tile + lsum visible to all warps

    load_slice(0, 0);
    CP_COMMIT();

    for (int t = 0; t < TILES; ++t) {
        if (t + 1 < TILES) load_slice(t + 1, (t + 1) & 1);
        CP_COMMIT();
        CP_WAIT1();
        __syncwarp();

        const uint32_t mh = wslice + (t & 1) * STG;
        const uint32_t ml = mh + 4096;

        // ---- weights prefetch (hidden under S mma) ----
        float wreg[2][2][4];   // [mf][nf][e]
        {
            const float* wp = wbase + (size_t)t * BM;
            #pragma unroll
            for (int mf = 0; mf < 2; ++mf)
                #pragma unroll
                for (int nf = 0; nf < 2; ++nf) {
                    float2 w0 = *(const float2*)(wp + (size_t)(mf * 16) * MT + nf * 8);
                    float2 w1 = *(const float2*)(wp + (size_t)(mf * 16 + 8) * MT + nf * 8);
                    wreg[mf][nf][0] = w0.x; wreg[mf][nf][1] = w0.y;
                    wreg[mf][nf][2] = w1.x; wreg[mf][nf][3] = w1.y;
                }
        }

        // ---- S = Q . Mem^T (m32 x n16 per warp), pass-major ----
        float sf[2][2][4];
        #pragma unroll
        for (int mf = 0; mf < 2; ++mf)
            #pragma unroll
            for (int nf = 0; nf < 2; ++nf)
                #pragma unroll
                for (int e = 0; e < 4; ++e) sf[mf][nf][e] = 0.f;

        #pragma unroll
        for (int k = 0; k < 8; ++k) {
            const int half = k >> 2;
            const int cb   = (k & 3) * 2;
            uint32_t Ah[8], Al[8];
            #pragma unroll
            for (int mf = 0; mf < 2; ++mf) {
                uint32_t ao = sw128((uint32_t)(half * 4096 + (mf * 16 + rowA) * 128
                                               + (cb + selA) * 16));
                ldsm_x4(Ah + mf * 4, sb + S_QH + ao);
                ldsm_x4(Al + mf * 4, sb + S_QL + ao);
            }
            uint32_t bo = sw128((uint32_t)(half * 2048 + sb_row * 128 + (cb + sb_sel) * 16));
            uint32_t Bh[4], Bl[4];
            ldsm_x4(Bh, mh + bo);
            ldsm_x4(Bl, ml + bo);

            #pragma unroll
            for (int mf = 0; mf < 2; ++mf)
                #pragma unroll
                for (int nf = 0; nf < 2; ++nf) mma_bf16(sf[mf][nf], Ah + mf * 4, Bh + nf * 2);
            #pragma unroll
            for (int mf = 0; mf < 2; ++mf)
                #pragma unroll
                for (int nf = 0; nf < 2; ++nf) mma_bf16(sf[mf][nf], Al + mf * 4, Bh + nf * 2);
            #pragma unroll
            for (int mf = 0; mf < 2; ++mf)
                #pragma unroll
                for (int nf = 0; nf < 2; ++nf) mma_bf16(sf[mf][nf], Ah + mf * 4, Bl + nf * 2);
        }

        // ---- weights * S, exp, split P into PV A-fragments (k16 over slice) ----
        uint32_t aPh[2][4], aPl[2][4];    // [mf][reg]
        #pragma unroll
        for (int mf = 0; mf < 2; ++mf) {
            float p[2][4];
            #pragma unroll
            for (int nf = 0; nf < 2; ++nf)
                #pragma unroll
                for (int e = 0; e < 4; ++e) {
                    float v = __expf(sf[mf][nf][e] * wreg[mf][nf][e]);
                    p[nf][e] = v;
                    rs[mf * 2 + (e >> 1)] += v;
                }
            uint32_t h0 = pack_bf16x2(p[0][0], p[0][1]);
            uint32_t h1 = pack_bf16x2(p[0][2], p[0][3]);
            uint32_t h2 = pack_bf16x2(p[1][0], p[1][1]);
            uint32_t h3 = pack_bf16x2(p[1][2], p[1][3]);
            aPh[mf][0] = h0; aPh[mf][1] = h1; aPh[mf][2] = h2; aPh[mf][3] = h3;
            __nv_bfloat162 b0 = *reinterpret_cast<__nv_bfloat162*>(&h0);
            __nv_bfloat162 b1 = *reinterpret_cast<__nv_bfloat162*>(&h1);
            __nv_bfloat162 b2 = *reinterpret_cast<__nv_bfloat162*>(&h2);
            __nv_bfloat162 b3 = *reinterpret_cast<__nv_bfloat162*>(&h3);
            aPl[mf][0] = pack_bf16x2(p[0][0] - __bfloat162float(b0.x),
                                     p[0][1] - __bfloat162float(b0.y));
            aPl[mf][1] = pack_bf16x2(p[0][2] - __bfloat162float(b1.x),
                                     p[0][3] - __bfloat162float(b1.y));
            aPl[mf][2] = pack_bf16x2(p[1][0] - __bfloat162float(b2.x),
                                     p[1][1] - __bfloat162float(b2.y));
            aPl[mf][3] = pack_bf16x2(p[1][2] - __bfloat162float(b3.x),
                                     p[1][3] - __bfloat162float(b3.y));
        }

        // ---- O += P . Mem (K = warp's 16 j-rows), groups of 4 d-frags ----
        #pragma unroll
        for (int nfg = 0; nfg < 16; nfg += 4) {
            uint32_t Bh[8], Bl[8];
            #pragma unroll
            for (int nfb = 0; nfb < 4; nfb += 2) {
                const int nf = nfg + nfb;
                uint32_t bo = sw128((uint32_t)((nf >> 3) * 2048 + pv_row * 128
                                    + ((nf & 7) + pv_sel) * 16));
                ldsm_x4t(Bh + nfb * 2, mh + bo);
                ldsm_x4t(Bl + nfb * 2, ml + bo);
            }
            #pragma unroll
            for (int mf = 0; mf < 2; ++mf)
                #pragma unroll
                for (int nfb = 0; nfb < 4; ++nfb)
                    mma_bf16(o_acc[mf][nfg + nfb], aPh[mf], Bh + nfb * 2);
            #pragma unroll
            for (int mf = 0; mf < 2; ++mf)
                #pragma unroll
                for (int nfb = 0; nfb < 4; ++nfb)
                    mma_bf16(o_acc[mf][nfg + nfb], aPl[mf], Bh + nfb * 2);
            #pragma unroll
            for (int mf = 0; mf < 2; ++mf)
                #pragma unroll
                for (int nfb = 0; nfb < 4; ++nfb)
                    mma_bf16(o_acc[mf][nfg + nfb], aPh[mf], Bl + nfb * 2);
        }
        __syncwarp();   // all lanes done reading stage before next overwrite
    }

    // ---- row-sum reduction: tig lanes, then across 8 warps ----
    #pragma unroll
    for (int r = 0; r < 4; ++r) {
        rs[r] += __shfl_xor_sync(0xffffffffu, rs[r], 1);
        rs[r] += __shfl_xor_sync(0xffffffffu, rs[r], 2);
    }
    if (tig == 0) {
        atomicAdd(&lsum[gid],      rs[0]);
        atomicAdd(&lsum[gid + 8],  rs[1]);
        atomicAdd(&lsum[16 + gid], rs[2]);
        atomicAdd(&lsum[24 + gid], rs[3]);
    }
    __syncthreads();   // all warps out of main loop (Q region now reusable)

    // ---- O reduction across warps via smem (reuse Q region) ----
    float* sO = (float*)(smem + S_QH);   // [32][128]
    for (int i = tid; i < 32 * 128; i += THREADS) sO[i] = 0.f;
    __syncthreads();
    #pragma unroll
    for (int mf = 0; mf < 2; ++mf)
        #pragma unroll
        for (int nf = 0; nf < 16; ++nf) {
            const int cbase = nf * 8 + tig * 2;
            const int r0 = mf * 16 + gid;
            atomicAdd(&sO[r0 * 128 + cbase],           o_acc[mf][nf][0]);
            atomicAdd(&sO[r0 * 128 + cbase + 1],       o_acc[mf][nf][1]);
            atomicAdd(&sO[(r0 + 8) * 128 + cbase],     o_acc[mf][nf][2]);
            atomicAdd(&sO[(r0 + 8) * 128 + cbase + 1], o_acc[mf][nf][3]);
        }
    __syncthreads();

    // ---- normalize + store ----
    for (int i = tid; i < 32 * 32; i += THREADS) {
        int r  = i >> 5;
        int c4 = (i & 31) * 4;
        float inv = 1.0f / lsum[r];
        float4 v = *(float4*)(&sO[r * 128 + c4]);
        v.x *= inv; v.y *= inv; v.z *= inv; v.w *= inv;
        *(float4*)(&out[(size_t)(q0 + r) * DD + c4]) = v;
    }
}

// ---------------- launch ----------------
extern "C" void kernel_launch(void* const* d_in, const int* in_sizes, int n_in,
                              void* d_out, int out_size)
{
    const float* query   = (const float*)d_in[0];
    const float* memory  = (const float*)d_in[1];
    const float* weights = (const float*)d_in[2];
    float* out = (float*)d_out;

    cudaFuncSetAttribute(attn_mma_kernel,
                         cudaFuncAttributeMaxDynamicSharedMemorySize, SMEM_TOTAL);

    prep_kernel<<<((QT + MT) * DD + 255) / 256, 256>>>(query, memory);
    attn_mma_kernel<<<QT / BQ, THREADS, SMEM_TOTAL>>>(weights, out);
}

// round 13
// speedup vs baseline: 1.3674x; 1.3674x over previous
#include <cuda_runtime.h>
#include <cuda_fp16.h>
#include <cstdint>
#include <math.h>

// ============================================================================
// ScaledDotAttention via mma.sync (HMMA fp16), sm_103-compatible PTX only.
//   out = softmax((Q.Mem^T/sqrt(D)) * W) . Mem     Q=4096, M=8192, D=128 fp32
//
// Round 13 vs R6 (157.9 us best; tensor/L1 both ~55-60%, 128/148 SMs used):
//  - fp16 hi/lo split (2^-11 rounding) allows 2-pass GEMMs:
//      S  = (Qh+Ql).Mh      PV = (Ph+Pl).Mh     (Mem-lo never needed)
//    -> ldsm.x4/warp/tile 80->48 (-40% L1), MMA 192->128 (-33% tensor),
//       Mem smem halved. Q stored UNSCALED (no subnormal Ql); 1/sqrt(d)
//       folded into the weights at load.
//  - persistent static schedule: grid=147 CTAs over 1024 (q-tile, j-chunk)
//    units, 7 contiguous units per CTA -> all SMs busy, 56 tiles/SM max
//    (was 64 on 128 SMs). Each q-tile = exactly 2 contributing CTAs ->
//    2 deterministic partial slabs + combine kernel (no cross-CTA atomics).
// ============================================================================

namespace {
constexpr int QT = 4096, MT = 8192, DD = 128;
constexpr int BQ = 32, BM = 128;
constexpr int THREADS = 256;
constexpr int NCTA = 147, UPC = 7, NUNITS = 1024;   // unit=(qt,jc): 128x8
constexpr float SCALE = 0.088388347648318440550f;   // 1/sqrt(128)

// smem layout (bytes)
constexpr int S_QH = 0;           // Q hi [2 d-halves][32 rows][128B] = 8KB
constexpr int S_QL = 8192;        // Q lo = 8KB
constexpr int S_M  = 16384;       // 4 pairs x 2 stages x 8KB (Mh only) = 64KB
constexpr int PSTRIDE = 16384;    // per-pair (2 stages)
constexpr int STG = 8192;         // one stage = 32 rows x 256B
constexpr int S_LSUM = S_M + 65536;   // 81920
constexpr int SMEM_TOTAL = S_LSUM + 256;
}

// preprocessed operands + partial-result slabs
__device__ __align__(16) __half g_q_h[QT * DD];
__device__ __align__(16) __half g_q_l[QT * DD];
__device__ __align__(16) __half g_m_h[MT * DD];
__device__ __align__(16) float g_out_part[2][(size_t)QT * DD];
__device__ float g_lsum_part[2][QT];

// ---------------- helpers ----------------
__device__ __forceinline__ uint32_t smem_to_u32(const void* p) {
    uint32_t a;
    asm("{ .reg .u64 t; cvta.to.shared.u64 t, %1; cvt.u32.u64 %0, t; }" : "=r"(a) : "l"(p));
    return a;
}
__device__ __forceinline__ uint32_t sw128(uint32_t o) { return o ^ ((o >> 3) & 0x70); }

__device__ __forceinline__ void ldsm_x4(uint32_t* r, uint32_t a) {
    asm volatile("ldmatrix.sync.aligned.m8n8.x4.shared.b16 {%0,%1,%2,%3}, [%4];"
                 : "=r"(r[0]), "=r"(r[1]), "=r"(r[2]), "=r"(r[3]) : "r"(a));
}
__device__ __forceinline__ void ldsm_x4t(uint32_t* r, uint32_t a) {
    asm volatile("ldmatrix.sync.aligned.m8n8.x4.trans.shared.b16 {%0,%1,%2,%3}, [%4];"
                 : "=r"(r[0]), "=r"(r[1]), "=r"(r[2]), "=r"(r[3]) : "r"(a));
}
__device__ __forceinline__ void mma_f16(float* c, const uint32_t* a, const uint32_t* b) {
    asm volatile("mma.sync.aligned.m16n8k16.row.col.f32.f16.f16.f32 "
                 "{%0,%1,%2,%3}, {%4,%5,%6,%7}, {%8,%9}, {%0,%1,%2,%3};"
                 : "+f"(c[0]), "+f"(c[1]), "+f"(c[2]), "+f"(c[3])
                 : "r"(a[0]), "r"(a[1]), "r"(a[2]), "r"(a[3]), "r"(b[0]), "r"(b[1]));
}
__device__ __forceinline__ uint32_t pack_h2(float a, float b) {
    __half2 v = __floats2half2_rn(a, b);   // .x = a
    return *reinterpret_cast<uint32_t*>(&v);
}
__device__ __forceinline__ float h2lo(uint32_t u) {
    __half2 v = *reinterpret_cast<__half2*>(&u); return __low2float(v);
}
__device__ __forceinline__ float h2hi(uint32_t u) {
    __half2 v = *reinterpret_cast<__half2*>(&u); return __high2float(v);
}
#define CP_ASYNC16(dst, src) \
    asm volatile("cp.async.cg.shared.global [%0], [%1], 16;" :: "r"(dst), "l"(src))
#define CP_COMMIT() asm volatile("cp.async.commit_group;" ::: "memory")
#define CP_WAIT1()  asm volatile("cp.async.wait_group 1;" ::: "memory")
#define BAR_PAIR(id) asm volatile("bar.sync %0, 64;" :: "r"(id) : "memory")

// ---------------- prep: fp32 -> fp16 hi/lo (Q) and hi (Mem) ----------------
__global__ void prep_kernel(const float* __restrict__ q, const float* __restrict__ m) {
    int idx = blockIdx.x * blockDim.x + threadIdx.x;
    if (idx < QT * DD) {
        float v = q[idx];                       // UNSCALED (scale folded into W)
        __half h = __float2half_rn(v);
        g_q_h[idx] = h;
        g_q_l[idx] = __float2half_rn(v - __half2float(h));
    }
    int midx = idx - QT * DD;
    if (midx >= 0 && midx < MT * DD)
        g_m_h[midx] = __float2half_rn(m[midx]);
}

// ---------------- main persistent kernel ----------------
__global__ __launch_bounds__(THREADS, 1)
void attn_mma_kernel(const float* __restrict__ weights)
{
    extern __shared__ char smem[];
    const uint32_t sb = smem_to_u32(smem);
    const int tid  = threadIdx.x;
    const int wid  = tid >> 5;
    const int lane = tid & 31;
    const int mw   = wid & 1;         // q-row group inside pair
    const int pw   = wid >> 1;        // pair id == j-quarter id (0..3)
    const int gid  = lane >> 2;
    const int tig  = lane & 3;
    const int qrow0 = mw * 16;
    const int j0w   = pw * 32;
    const int barid = 1 + pw;
    const int c = blockIdx.x;

    const int u0 = c * UPC;
    const int u1 = min(u0 + UPC, NUNITS);
    if (u0 >= NUNITS) return;
    const int qt_a = u0 >> 3, qt_b = (u1 - 1) >> 3;

    float* lsum = (float*)(smem + S_LSUM);

    // per-lane addressing (identical to R6)
    const int rowA   = qrow0 + (lane & 15);
    const int selA   = lane >> 4;
    const int sb_row = ((lane >> 4) & 1) * 8 + (lane & 7);
    const int sb_sel = (lane >> 3) & 1;
    const int pv_row = lane & 15;
    const int pv_sel = lane >> 4;

    const uint32_t pair_base = sb + S_M + pw * PSTRIDE;

    for (int qt = qt_a; qt <= qt_b; ++qt) {
        const int s0 = max(u0, qt * 8) - qt * 8;     // first j-chunk
        const int s1 = min(u1, qt * 8 + 8) - qt * 8; // end j-chunk
        const int t_beg = s0 * 8, t_end = s1 * 8;    // tile range (global 0..63)
        const int q0 = qt * BQ;
        const int slot = c - (8 * qt) / 7;           // 0 or 1, deterministic

        if (tid < 32) lsum[tid] = 0.f;

        // ---- load Q tile hi/lo ----
        for (int it = tid; it < 32 * 16; it += THREADS) {
            int row = it >> 4, ch = it & 15;
            uint32_t o = sw128((uint32_t)((ch >> 3) * 4096 + row * 128 + (ch & 7) * 16));
            *(uint4*)(smem + S_QH + o) = *(const uint4*)(g_q_h + (size_t)(q0 + row) * DD + ch * 8);
            *(uint4*)(smem + S_QL + o) = *(const uint4*)(g_q_l + (size_t)(q0 + row) * DD + ch * 8);
        }
        __syncthreads();

        float o_acc[16][4];
        #pragma unroll
        for (int nf = 0; nf < 16; ++nf)
            #pragma unroll
            for (int e = 0; e < 4; ++e) o_acc[nf][e] = 0.f;
        float rs0 = 0.f, rs1 = 0.f;

        const float* wbase = weights + (size_t)(q0 + qrow0 + gid) * MT + j0w + tig * 2;

        // pair's 64 threads load the pair's 32-row quarter (Mh only)
        auto load_quarter = [&](int t, int buf) {
            const int m0 = t * BM + j0w;
            const uint32_t qb = pair_base + buf * STG;
            int it = tid & 63;
            #pragma unroll
            for (int rep = 0; rep < 8; ++rep, it += 64) {   // 512 items / 64 thr
                int row = it >> 4, ch = it & 15;
                uint32_t o = sw128((uint32_t)((ch >> 3) * 4096 + row * 128 + (ch & 7) * 16));
                CP_ASYNC16(qb + o, (const void*)(g_m_h + (size_t)(m0 + row) * DD + ch * 8));
            }
        };

        load_quarter(t_beg, t_beg & 1);
        CP_COMMIT();

        for (int t = t_beg; t < t_end; ++t) {
            if (t + 1 < t_end) load_quarter(t + 1, (t + 1) & 1);
            CP_COMMIT();
            CP_WAIT1();
            BAR_PAIR(barid);

            const uint32_t mh = pair_base + (t & 1) * STG;

            // ---- weights prefetch, pre-scaled by 1/sqrt(d) ----
            float wreg[4][4];
            {
                const float* wp = wbase + (size_t)t * BM;
                #pragma unroll
                for (int nf = 0; nf < 4; ++nf) {
                    float2 w0 = *(const float2*)(wp + nf * 8);
                    float2 w1 = *(const float2*)(wp + nf * 8 + (size_t)8 * MT);
                    wreg[nf][0] = w0.x * SCALE; wreg[nf][1] = w0.y * SCALE;
                    wreg[nf][2] = w1.x * SCALE; wreg[nf][3] = w1.y * SCALE;
                }
            }

            // ---- S = Q . Mem^T (16x32 per warp), 2 passes: (Qh+Ql).Mh ----
            float sf[4][4];
            #pragma unroll
            for (int nf = 0; nf < 4; ++nf)
                #pragma unroll
                for (int e = 0; e < 4; ++e) sf[nf][e] = 0.f;

            #pragma unroll
            for (int k = 0; k < 8; ++k) {
                const int half = k >> 2;
                const int cb   = (k & 3) * 2;
                uint32_t ao = sw128((uint32_t)(half * 4096 + rowA * 128 + (cb + selA) * 16));
                uint32_t Ah[4], Al[4];
                ldsm_x4(Ah, sb + S_QH + ao);
                ldsm_x4(Al, sb + S_QL + ao);

                uint32_t Bh[8];
                #pragma unroll
                for (int nfb = 0; nfb < 4; nfb += 2) {
                    uint32_t bo = sw128((uint32_t)(half * 4096
                                        + (nfb * 8 + sb_row) * 128
                                        + (cb + sb_sel) * 16));
                    ldsm_x4(Bh + nfb * 2, mh + bo);
                }
                #pragma unroll
                for (int nf = 0; nf < 4; ++nf) mma_f16(sf[nf], Ah, Bh + nf * 2);
                #pragma unroll
                for (int nf = 0; nf < 4; ++nf) mma_f16(sf[nf], Al, Bh + nf * 2);
            }

            // ---- weights * S, exp, split P into fp16 hi/lo A-fragments ----
            uint32_t aPh[2][4], aPl[2][4];
            #pragma unroll
            for (int nf = 0; nf < 4; ++nf) {
                float p[4];
                #pragma unroll
                for (int e = 0; e < 4; ++e) p[e] = __expf(sf[nf][e] * wreg[nf][e]);
                rs0 += p[0] + p[1];
                rs1 += p[2] + p[3];

                uint32_t h01 = pack_h2(p[0], p[1]);
                uint32_t h23 = pack_h2(p[2], p[3]);
                const int kf = nf >> 1;
                const int hi = (nf & 1) * 2;
                aPh[kf][hi]     = h01;
                aPh[kf][hi + 1] = h23;
                aPl[kf][hi]     = pack_h2(p[0] - h2lo(h01), p[1] - h2hi(h01));
                aPl[kf][hi + 1] = pack_h2(p[2] - h2lo(h23), p[3] - h2hi(h23));
            }

            // ---- O += P . Mem, 2 passes: (Ph+Pl).Mh ----
            #pragma unroll
            for (int kf = 0; kf < 2; ++kf) {
                const int jb = (kf * 16 + pv_row) * 128;
                #pragma unroll
                for (int nfg = 0; nfg < 16; nfg += 4) {
                    uint32_t Bh[8];
                    #pragma unroll
                    for (int nfb = 0; nfb < 4; nfb += 2) {
                        const int nf = nfg + nfb;
                        uint32_t bo = sw128((uint32_t)((nf >> 3) * 4096 + jb
                                            + ((nf & 7) + pv_sel) * 16));
                        ldsm_x4t(Bh + nfb * 2, mh + bo);
                    }
                    #pragma unroll
                    for (int nfb = 0; nfb < 4; ++nfb)
                        mma_f16(o_acc[nfg + nfb], aPh[kf], Bh + nfb * 2);
                    #pragma unroll
                    for (int nfb = 0; nfb < 4; ++nfb)
                        mma_f16(o_acc[nfg + nfb], aPl[kf], Bh + nfb * 2);
                }
            }
            BAR_PAIR(barid);
        }

        // ---- segment epilogue: reduce + write partial slabs ----
        rs0 += __shfl_xor_sync(0xffffffffu, rs0, 1);
        rs0 += __shfl_xor_sync(0xffffffffu, rs0, 2);
        rs1 += __shfl_xor_sync(0xffffffffu, rs1, 1);
        rs1 += __shfl_xor_sync(0xffffffffu, rs1, 2);
        if (tig == 0) {
            atomicAdd(&lsum[qrow0 + gid], rs0);
            atomicAdd(&lsum[qrow0 + gid + 8], rs1);
        }
        __syncthreads();

        float* sO = (float*)(smem + S_QH);   // reuse Q region: [32][128] fp32
        for (int i = tid; i < 32 * 128; i += THREADS) sO[i] = 0.f;
        __syncthreads();
        #pragma unroll
        for (int nf = 0; nf < 16; ++nf) {
            const int cbase = nf * 8 + tig * 2;
            const int r0 = qrow0 + gid;
            atomicAdd(&sO[r0 * 128 + cbase],           o_acc[nf][0]);
            atomicAdd(&sO[r0 * 128 + cbase + 1],       o_acc[nf][1]);
            atomicAdd(&sO[(r0 + 8) * 128 + cbase],     o_acc[nf][2]);
            atomicAdd(&sO[(r0 + 8) * 128 + cbase + 1], o_acc[nf][3]);
        }
        __syncthreads();

        for (int i = tid; i < 32 * 32; i += THREADS) {
            int r  = i >> 5;
            int c4 = (i & 31) * 4;
            float4 v = *(float4*)(&sO[r * 128 + c4]);
            *(float4*)(&g_out_part[slot][(size_t)(q0 + r) * DD + c4]) = v;
        }
        if (tid < 32) g_lsum_part[slot][q0 + tid] = lsum[tid];
        __syncthreads();   // done with sO/lsum before next segment's Q load
    }
}

// ---------------- combine: out = (p0+p1)/(l0+l1) ----------------
__global__ void combine_kernel(float* __restrict__ out) {
    int idx = blockIdx.x * blockDim.x + threadIdx.x;
    if (idx >= QT * (DD / 4)) return;
    int r  = idx >> 5;
    int c4 = (idx & 31) * 4;
    float inv = 1.0f / (g_lsum_part[0][r] + g_lsum_part[1][r]);
    float4 a = *(float4*)(&g_out_part[0][(size_t)r * DD + c4]);
    float4 b = *(float4*)(&g_out_part[1][(size_t)r * DD + c4]);
    float4 v;
    v.x = (a.x + b.x) * inv; v.y = (a.y + b.y) * inv;
    v.z = (a.z + b.z) * inv; v.w = (a.w + b.w) * inv;
    *(float4*)(&out[(size_t)r * DD + c4]) = v;
}

// ---------------- launch ----------------
extern "C" void kernel_launch(void* const* d_in, const int* in_sizes, int n_in,
                              void* d_out, int out_size)
{
    const float* query   = (const float*)d_in[0];
    const float* memory  = (const float*)d_in[1];
    const float* weights = (const float*)d_in[2];
    float* out = (float*)d_out;

    cudaFuncSetAttribute(attn_mma_kernel,
                         cudaFuncAttributeMaxDynamicSharedMemorySize, SMEM_TOTAL);

    prep_kernel<<<((QT + MT) * DD) / 256, 256>>>(query, memory);
    attn_mma_kernel<<<NCTA, THREADS, SMEM_TOTAL>>>(weights);
    combine_kernel<<<(QT * (DD / 4) + 255) / 256, 256>>>(out);
}

// round 14
// speedup vs baseline: 1.6927x; 1.2379x over previous
#include <cuda_runtime.h>
#include <cuda_fp16.h>
#include <cstdint>
#include <math.h>

// ============================================================================
// ScaledDotAttention via mma.sync (HMMA fp16), sm_103-compatible PTX only.
//   out = softmax((Q.Mem^T/sqrt(D)) * W) . Mem     Q=4096, M=8192, D=128 fp32
//
// Round 14 vs R13 (120.4 us, rel_err 7.9e-5, 12x error margin):
//  - PURE fp16 single-pass GEMMs: S = Qh.Mh, PV = Ph.Mh (compensation passes
//    dropped). Error model (validated by R13's on-prediction 7.9e-5):
//    ~3e-4 from S rounding + ~4e-4 from PV rounding -> ~5e-4 total < 1e-3.
//  - MMA per warp per tile 128 -> 64, ldsm.x4 48 -> 40, Q-lo eliminated
//    (smem 82 -> 74 KB, regs down).
//  - prep kernel float4-vectorized (no Ql to produce).
//  - persistent 147-CTA static schedule + 2-slab combine unchanged (R13).
// ============================================================================

namespace {
constexpr int QT = 4096, MT = 8192, DD = 128;
constexpr int BQ = 32, BM = 128;
constexpr int THREADS = 256;
constexpr int NCTA = 147, UPC = 7, NUNITS = 1024;   // unit=(qt,jc): 128x8
constexpr float SCALE = 0.088388347648318440550f;   // 1/sqrt(128)

// smem layout (bytes)
constexpr int S_QH = 0;           // Q hi [2 d-halves][32 rows][128B] = 8KB
constexpr int S_M  = 8192;        // 4 pairs x 2 stages x 8KB (Mh) = 64KB
constexpr int PSTRIDE = 16384;    // per-pair (2 stages)
constexpr int STG = 8192;         // one stage = 32 rows x 256B
constexpr int S_LSUM = S_M + 65536;   // 73728
constexpr int SMEM_TOTAL = S_LSUM + 256;
// note: epilogue sO ([32][128] fp32 = 16KB) reuses the S_M region
}

// preprocessed operands + partial-result slabs
__device__ __align__(16) __half g_q_h[QT * DD];
__device__ __align__(16) __half g_m_h[MT * DD];
__device__ __align__(16) float g_out_part[2][(size_t)QT * DD];
__device__ float g_lsum_part[2][QT];

// ---------------- helpers ----------------
__device__ __forceinline__ uint32_t smem_to_u32(const void* p) {
    uint32_t a;
    asm("{ .reg .u64 t; cvta.to.shared.u64 t, %1; cvt.u32.u64 %0, t; }" : "=r"(a) : "l"(p));
    return a;
}
__device__ __forceinline__ uint32_t sw128(uint32_t o) { return o ^ ((o >> 3) & 0x70); }

__device__ __forceinline__ void ldsm_x4(uint32_t* r, uint32_t a) {
    asm volatile("ldmatrix.sync.aligned.m8n8.x4.shared.b16 {%0,%1,%2,%3}, [%4];"
                 : "=r"(r[0]), "=r"(r[1]), "=r"(r[2]), "=r"(r[3]) : "r"(a));
}
__device__ __forceinline__ void ldsm_x4t(uint32_t* r, uint32_t a) {
    asm volatile("ldmatrix.sync.aligned.m8n8.x4.trans.shared.b16 {%0,%1,%2,%3}, [%4];"
                 : "=r"(r[0]), "=r"(r[1]), "=r"(r[2]), "=r"(r[3]) : "r"(a));
}
__device__ __forceinline__ void mma_f16(float* c, const uint32_t* a, const uint32_t* b) {
    asm volatile("mma.sync.aligned.m16n8k16.row.col.f32.f16.f16.f32 "
                 "{%0,%1,%2,%3}, {%4,%5,%6,%7}, {%8,%9}, {%0,%1,%2,%3};"
                 : "+f"(c[0]), "+f"(c[1]), "+f"(c[2]), "+f"(c[3])
                 : "r"(a[0]), "r"(a[1]), "r"(a[2]), "r"(a[3]), "r"(b[0]), "r"(b[1]));
}
__device__ __forceinline__ uint32_t pack_h2(float a, float b) {
    __half2 v = __floats2half2_rn(a, b);   // .x = a
    return *reinterpret_cast<uint32_t*>(&v);
}
#define CP_ASYNC16(dst, src) \
    asm volatile("cp.async.cg.shared.global [%0], [%1], 16;" :: "r"(dst), "l"(src))
#define CP_COMMIT() asm volatile("cp.async.commit_group;" ::: "memory")
#define CP_WAIT1()  asm volatile("cp.async.wait_group 1;" ::: "memory")
#define BAR_PAIR(id) asm volatile("bar.sync %0, 64;" :: "r"(id) : "memory")

// ---------------- prep: fp32 -> fp16, float4 vectorized ----------------
__global__ void prep_kernel(const float* __restrict__ q, const float* __restrict__ m) {
    int i4 = (blockIdx.x * blockDim.x + threadIdx.x) * 4;
    if (i4 < QT * DD) {
        float4 v = *(const float4*)(q + i4);
        *(__half2*)(g_q_h + i4)     = __floats2half2_rn(v.x, v.y);
        *(__half2*)(g_q_h + i4 + 2) = __floats2half2_rn(v.z, v.w);
    } else {
        int mi = i4 - QT * DD;
        if (mi < MT * DD) {
            float4 v = *(const float4*)(m + mi);
            *(__half2*)(g_m_h + mi)     = __floats2half2_rn(v.x, v.y);
            *(__half2*)(g_m_h + mi + 2) = __floats2half2_rn(v.z, v.w);
        }
    }
}

// ---------------- main persistent kernel ----------------
__global__ __launch_bounds__(THREADS, 1)
void attn_mma_kernel(const float* __restrict__ weights)
{
    extern __shared__ char smem[];
    const uint32_t sb = smem_to_u32(smem);
    const int tid  = threadIdx.x;
    const int wid  = tid >> 5;
    const int lane = tid & 31;
    const int mw   = wid & 1;         // q-row group inside pair
    const int pw   = wid >> 1;        // pair id == j-quarter id (0..3)
    const int gid  = lane >> 2;
    const int tig  = lane & 3;
    const int qrow0 = mw * 16;
    const int j0w   = pw * 32;
    const int barid = 1 + pw;
    const int c = blockIdx.x;

    const int u0 = c * UPC;
    const int u1 = min(u0 + UPC, NUNITS);
    if (u0 >= NUNITS) return;
    const int qt_a = u0 >> 3, qt_b = (u1 - 1) >> 3;

    float* lsum = (float*)(smem + S_LSUM);

    // per-lane addressing (R6 geometry)
    const int rowA   = qrow0 + (lane & 15);
    const int selA   = lane >> 4;
    const int sb_row = ((lane >> 4) & 1) * 8 + (lane & 7);
    const int sb_sel = (lane >> 3) & 1;
    const int pv_row = lane & 15;
    const int pv_sel = lane >> 4;

    const uint32_t pair_base = sb + S_M + pw * PSTRIDE;

    for (int qt = qt_a; qt <= qt_b; ++qt) {
        const int s0 = max(u0, qt * 8) - qt * 8;
        const int s1 = min(u1, qt * 8 + 8) - qt * 8;
        const int t_beg = s0 * 8, t_end = s1 * 8;
        const int q0 = qt * BQ;
        const int slot = c - (8 * qt) / 7;           // 0 or 1, deterministic

        if (tid < 32) lsum[tid] = 0.f;

        // ---- load Q tile (hi only) ----
        for (int it = tid; it < 32 * 16; it += THREADS) {
            int row = it >> 4, ch = it & 15;
            uint32_t o = sw128((uint32_t)((ch >> 3) * 4096 + row * 128 + (ch & 7) * 16));
            *(uint4*)(smem + S_QH + o) = *(const uint4*)(g_q_h + (size_t)(q0 + row) * DD + ch * 8);
        }
        __syncthreads();

        float o_acc[16][4];
        #pragma unroll
        for (int nf = 0; nf < 16; ++nf)
            #pragma unroll
            for (int e = 0; e < 4; ++e) o_acc[nf][e] = 0.f;
        float rs0 = 0.f, rs1 = 0.f;

        const float* wbase = weights + (size_t)(q0 + qrow0 + gid) * MT + j0w + tig * 2;

        auto load_quarter = [&](int t, int buf) {
            const int m0 = t * BM + j0w;
            const uint32_t qb = pair_base + buf * STG;
            int it = tid & 63;
            #pragma unroll
            for (int rep = 0; rep < 8; ++rep, it += 64) {   // 512 items / 64 thr
                int row = it >> 4, ch = it & 15;
                uint32_t o = sw128((uint32_t)((ch >> 3) * 4096 + row * 128 + (ch & 7) * 16));
                CP_ASYNC16(qb + o, (const void*)(g_m_h + (size_t)(m0 + row) * DD + ch * 8));
            }
        };

        load_quarter(t_beg, t_beg & 1);
        CP_COMMIT();

        for (int t = t_beg; t < t_end; ++t) {
            if (t + 1 < t_end) load_quarter(t + 1, (t + 1) & 1);
            CP_COMMIT();
            CP_WAIT1();
            BAR_PAIR(barid);

            const uint32_t mh = pair_base + (t & 1) * STG;

            // ---- weights prefetch, pre-scaled by 1/sqrt(d) ----
            float wreg[4][4];
            {
                const float* wp = wbase + (size_t)t * BM;
                #pragma unroll
                for (int nf = 0; nf < 4; ++nf) {
                    float2 w0 = *(const float2*)(wp + nf * 8);
                    float2 w1 = *(const float2*)(wp + nf * 8 + (size_t)8 * MT);
                    wreg[nf][0] = w0.x * SCALE; wreg[nf][1] = w0.y * SCALE;
                    wreg[nf][2] = w1.x * SCALE; wreg[nf][3] = w1.y * SCALE;
                }
            }

            // ---- S = Qh . Mh^T (16x32 per warp), SINGLE pass ----
            float sf[4][4];
            #pragma unroll
            for (int nf = 0; nf < 4; ++nf)
                #pragma unroll
                for (int e = 0; e < 4; ++e) sf[nf][e] = 0.f;

            #pragma unroll
            for (int k = 0; k < 8; ++k) {
                const int half = k >> 2;
                const int cb   = (k & 3) * 2;
                uint32_t ao = sw128((uint32_t)(half * 4096 + rowA * 128 + (cb + selA) * 16));
                uint32_t Ah[4];
                ldsm_x4(Ah, sb + S_QH + ao);

                uint32_t Bh[8];
                #pragma unroll
                for (int nfb = 0; nfb < 4; nfb += 2) {
                    uint32_t bo = sw128((uint32_t)(half * 4096
                                        + (nfb * 8 + sb_row) * 128
                                        + (cb + sb_sel) * 16));
                    ldsm_x4(Bh + nfb * 2, mh + bo);
                }
                #pragma unroll
                for (int nf = 0; nf < 4; ++nf) mma_f16(sf[nf], Ah, Bh + nf * 2);
            }

            // ---- weights * S, exp, pack P to fp16 A-fragments ----
            uint32_t aPh[2][4];
            #pragma unroll
            for (int nf = 0; nf < 4; ++nf) {
                float p[4];
                #pragma unroll
                for (int e = 0; e < 4; ++e) p[e] = __expf(sf[nf][e] * wreg[nf][e]);
                rs0 += p[0] + p[1];
                rs1 += p[2] + p[3];
                const int kf = nf >> 1;
                const int hi = (nf & 1) * 2;
                aPh[kf][hi]     = pack_h2(p[0], p[1]);
                aPh[kf][hi + 1] = pack_h2(p[2], p[3]);
            }

            // ---- O += Ph . Mh, SINGLE pass ----
            #pragma unroll
            for (int kf = 0; kf < 2; ++kf) {
                const int jb = (kf * 16 + pv_row) * 128;
                #pragma unroll
                for (int nfg = 0; nfg < 16; nfg += 4) {
                    uint32_t Bh[8];
                    #pragma unroll
                    for (int nfb = 0; nfb < 4; nfb += 2) {
                        const int nf = nfg + nfb;
                        uint32_t bo = sw128((uint32_t)((nf >> 3) * 4096 + jb
                                            + ((nf & 7) + pv_sel) * 16));
                        ldsm_x4t(Bh + nfb * 2, mh + bo);
                    }
                    #pragma unroll
                    for (int nfb = 0; nfb < 4; ++nfb)
                        mma_f16(o_acc[nfg + nfb], aPh[kf], Bh + nfb * 2);
                }
            }
            BAR_PAIR(barid);
        }

        // ---- segment epilogue: reduce + write partial slabs ----
        rs0 += __shfl_xor_sync(0xffffffffu, rs0, 1);
        rs0 += __shfl_xor_sync(0xffffffffu, rs0, 2);
        rs1 += __shfl_xor_sync(0xffffffffu, rs1, 1);
        rs1 += __shfl_xor_sync(0xffffffffu, rs1, 2);
        if (tig == 0) {
            atomicAdd(&lsum[qrow0 + gid], rs0);
            atomicAdd(&lsum[qrow0 + gid + 8], rs1);
        }
        __syncthreads();

        float* sO = (float*)(smem + S_M);   // reuse Mem region: [32][128] fp32
        for (int i = tid; i < 32 * 128; i += THREADS) sO[i] = 0.f;
        __syncthreads();
        #pragma unroll
        for (int nf = 0; nf < 16; ++nf) {
            const int cbase = nf * 8 + tig * 2;
            const int r0 = qrow0 + gid;
            atomicAdd(&sO[r0 * 128 + cbase],           o_acc[nf][0]);
            atomicAdd(&sO[r0 * 128 + cbase + 1],       o_acc[nf][1]);
            atomicAdd(&sO[(r0 + 8) * 128 + cbase],     o_acc[nf][2]);
            atomicAdd(&sO[(r0 + 8) * 128 + cbase + 1], o_acc[nf][3]);
        }
        __syncthreads();

        for (int i = tid; i < 32 * 32; i += THREADS) {
            int r  = i >> 5;
            int c4 = (i & 31) * 4;
            float4 v = *(float4*)(&sO[r * 128 + c4]);
            *(float4*)(&g_out_part[slot][(size_t)(q0 + r) * DD + c4]) = v;
        }
        if (tid < 32) g_lsum_part[slot][q0 + tid] = lsum[tid];
        __syncthreads();   // done with sO/lsum before next segment
    }
}

// ---------------- combine: out = (p0+p1)/(l0+l1) ----------------
__global__ void combine_kernel(float* __restrict__ out) {
    int idx = blockIdx.x * blockDim.x + threadIdx.x;
    if (idx >= QT * (DD / 4)) return;
    int r  = idx >> 5;
    int c4 = (idx & 31) * 4;
    float inv = 1.0f / (g_lsum_part[0][r] + g_lsum_part[1][r]);
    float4 a = *(float4*)(&g_out_part[0][(size_t)r * DD + c4]);
    float4 b = *(float4*)(&g_out_part[1][(size_t)r * DD + c4]);
    float4 v;
    v.x = (a.x + b.x) * inv; v.y = (a.y + b.y) * inv;
    v.z = (a.z + b.z) * inv; v.w = (a.w + b.w) * inv;
    *(float4*)(&out[(size_t)r * DD + c4]) = v;
}

// ---------------- launch ----------------
extern "C" void kernel_launch(void* const* d_in, const int* in_sizes, int n_in,
                              void* d_out, int out_size)
{
    const float* query   = (const float*)d_in[0];
    const float* memory  = (const float*)d_in[1];
    const float* weights = (const float*)d_in[2];
    float* out = (float*)d_out;

    cudaFuncSetAttribute(attn_mma_kernel,
                         cudaFuncAttributeMaxDynamicSharedMemorySize, SMEM_TOTAL);

    prep_kernel<<<((QT + MT) * DD / 4 + 255) / 256, 256>>>(query, memory);
    attn_mma_kernel<<<NCTA, THREADS, SMEM_TOTAL>>>(weights);
    combine_kernel<<<(QT * (DD / 4) + 255) / 256, 256>>>(out);
}

// round 15
// speedup vs baseline: 1.8170x; 1.0735x over previous
#include <cuda_runtime.h>
#include <cuda_fp16.h>
#include <cstdint>
#include <math.h>

// ============================================================================
// ScaledDotAttention via mma.sync (HMMA fp16), sm_103-compatible PTX only.
//   out = softmax((Q.Mem^T/sqrt(D)) * W) . Mem     Q=4096, M=8192, D=128 fp32
//
// Round 15 vs R14 (97.2 us, rel_err 2.3e-4):
//  - REGISTER-RESIDENT Q: A(Q) fragments hoisted into 32 regs once per q-tile
//    segment -> ldsm.x4 per warp per tile 40 -> 32 (-20% smem crossbar)
//  - barrier halving: prefetch issued AFTER the pair barrier (wait -> bar ->
//    prefetch -> compute) makes the trailing WAR barrier unnecessary with the
//    2-stage ring -> 1 bar.sync per tile (was 2)
//  - math unchanged: single-pass fp16 S = Qh.Mh, PV = Ph.Mh; persistent
//    147-CTA static schedule + 2-slab combine (R13/R14)
// ============================================================================

namespace {
constexpr int QT = 4096, MT = 8192, DD = 128;
constexpr int BQ = 32, BM = 128;
constexpr int THREADS = 256;
constexpr int NCTA = 147, UPC = 7, NUNITS = 1024;   // unit=(qt,jc): 128x8
constexpr float SCALE = 0.088388347648318440550f;   // 1/sqrt(128)

// smem layout (bytes)
constexpr int S_QH = 0;           // Q hi [2 d-halves][32 rows][128B] = 8KB
constexpr int S_M  = 8192;        // 4 pairs x 2 stages x 8KB (Mh) = 64KB
constexpr int PSTRIDE = 16384;    // per-pair (2 stages)
constexpr int STG = 8192;         // one stage = 32 rows x 256B
constexpr int S_LSUM = S_M + 65536;   // 73728
constexpr int SMEM_TOTAL = S_LSUM + 256;
// epilogue sO ([32][128] fp32 = 16KB) reuses the S_M region
}

// preprocessed operands + partial-result slabs
__device__ __align__(16) __half g_q_h[QT * DD];
__device__ __align__(16) __half g_m_h[MT * DD];
__device__ __align__(16) float g_out_part[2][(size_t)QT * DD];
__device__ float g_lsum_part[2][QT];

// ---------------- helpers ----------------
__device__ __forceinline__ uint32_t smem_to_u32(const void* p) {
    uint32_t a;
    asm("{ .reg .u64 t; cvta.to.shared.u64 t, %1; cvt.u32.u64 %0, t; }" : "=r"(a) : "l"(p));
    return a;
}
__device__ __forceinline__ uint32_t sw128(uint32_t o) { return o ^ ((o >> 3) & 0x70); }

__device__ __forceinline__ void ldsm_x4(uint32_t* r, uint32_t a) {
    asm volatile("ldmatrix.sync.aligned.m8n8.x4.shared.b16 {%0,%1,%2,%3}, [%4];"
                 : "=r"(r[0]), "=r"(r[1]), "=r"(r[2]), "=r"(r[3]) : "r"(a));
}
__device__ __forceinline__ void ldsm_x4t(uint32_t* r, uint32_t a) {
    asm volatile("ldmatrix.sync.aligned.m8n8.x4.trans.shared.b16 {%0,%1,%2,%3}, [%4];"
                 : "=r"(r[0]), "=r"(r[1]), "=r"(r[2]), "=r"(r[3]) : "r"(a));
}
__device__ __forceinline__ void mma_f16(float* c, const uint32_t* a, const uint32_t* b) {
    asm volatile("mma.sync.aligned.m16n8k16.row.col.f32.f16.f16.f32 "
                 "{%0,%1,%2,%3}, {%4,%5,%6,%7}, {%8,%9}, {%0,%1,%2,%3};"
                 : "+f"(c[0]), "+f"(c[1]), "+f"(c[2]), "+f"(c[3])
                 : "r"(a[0]), "r"(a[1]), "r"(a[2]), "r"(a[3]), "r"(b[0]), "r"(b[1]));
}
__device__ __forceinline__ uint32_t pack_h2(float a, float b) {
    __half2 v = __floats2half2_rn(a, b);   // .x = a
    return *reinterpret_cast<uint32_t*>(&v);
}
#define CP_ASYNC16(dst, src) \
    asm volatile("cp.async.cg.shared.global [%0], [%1], 16;" :: "r"(dst), "l"(src))
#define CP_COMMIT() asm volatile("cp.async.commit_group;" ::: "memory")
#define CP_WAIT0()  asm volatile("cp.async.wait_group 0;" ::: "memory")
#define BAR_PAIR(id) asm volatile("bar.sync %0, 64;" :: "r"(id) : "memory")

// ---------------- prep: fp32 -> fp16, float4 vectorized ----------------
__global__ void prep_kernel(const float* __restrict__ q, const float* __restrict__ m) {
    int i4 = (blockIdx.x * blockDim.x + threadIdx.x) * 4;
    if (i4 < QT * DD) {
        float4 v = *(const float4*)(q + i4);
        *(__half2*)(g_q_h + i4)     = __floats2half2_rn(v.x, v.y);
        *(__half2*)(g_q_h + i4 + 2) = __floats2half2_rn(v.z, v.w);
    } else {
        int mi = i4 - QT * DD;
        if (mi < MT * DD) {
            float4 v = *(const float4*)(m + mi);
            *(__half2*)(g_m_h + mi)     = __floats2half2_rn(v.x, v.y);
            *(__half2*)(g_m_h + mi + 2) = __floats2half2_rn(v.z, v.w);
        }
    }
}

// ---------------- main persistent kernel ----------------
__global__ __launch_bounds__(THREADS, 1)
void attn_mma_kernel(const float* __restrict__ weights)
{
    extern __shared__ char smem[];
    const uint32_t sb = smem_to_u32(smem);
    const int tid  = threadIdx.x;
    const int wid  = tid >> 5;
    const int lane = tid & 31;
    const int mw   = wid & 1;         // q-row group inside pair
    const int pw   = wid >> 1;        // pair id == j-quarter id (0..3)
    const int gid  = lane >> 2;
    const int tig  = lane & 3;
    const int qrow0 = mw * 16;
    const int j0w   = pw * 32;
    const int barid = 1 + pw;
    const int c = blockIdx.x;

    const int u0 = c * UPC;
    const int u1 = min(u0 + UPC, NUNITS);
    if (u0 >= NUNITS) return;
    const int qt_a = u0 >> 3, qt_b = (u1 - 1) >> 3;

    float* lsum = (float*)(smem + S_LSUM);

    // per-lane addressing (R6 geometry)
    const int rowA   = qrow0 + (lane & 15);
    const int selA   = lane >> 4;
    const int sb_row = ((lane >> 4) & 1) * 8 + (lane & 7);
    const int sb_sel = (lane >> 3) & 1;
    const int pv_row = lane & 15;
    const int pv_sel = lane >> 4;

    const uint32_t pair_base = sb + S_M + pw * PSTRIDE;

    for (int qt = qt_a; qt <= qt_b; ++qt) {
        const int s0 = max(u0, qt * 8) - qt * 8;
        const int s1 = min(u1, qt * 8 + 8) - qt * 8;
        const int t_beg = s0 * 8, t_end = s1 * 8;
        const int q0 = qt * BQ;
        const int slot = c - (8 * qt) / 7;           // 0 or 1, deterministic

        if (tid < 32) lsum[tid] = 0.f;

        // ---- load Q tile to smem, then hoist A-fragments to registers ----
        for (int it = tid; it < 32 * 16; it += THREADS) {
            int row = it >> 4, ch = it & 15;
            uint32_t o = sw128((uint32_t)((ch >> 3) * 4096 + row * 128 + (ch & 7) * 16));
            *(uint4*)(smem + S_QH + o) = *(const uint4*)(g_q_h + (size_t)(q0 + row) * DD + ch * 8);
        }
        __syncthreads();

        uint32_t Aq[8][4];   // A(Q) fragments, resident for the whole segment
        #pragma unroll
        for (int k = 0; k < 8; ++k) {
            const int half = k >> 2;
            const int cb   = (k & 3) * 2;
            uint32_t ao = sw128((uint32_t)(half * 4096 + rowA * 128 + (cb + selA) * 16));
            ldsm_x4(Aq[k], sb + S_QH + ao);
        }

        float o_acc[16][4];
        #pragma unroll
        for (int nf = 0; nf < 16; ++nf)
            #pragma unroll
            for (int e = 0; e < 4; ++e) o_acc[nf][e] = 0.f;
        float rs0 = 0.f, rs1 = 0.f;

        const float* wbase = weights + (size_t)(q0 + qrow0 + gid) * MT + j0w + tig * 2;

        auto load_quarter = [&](int t, int buf) {
            const int m0 = t * BM + j0w;
            const uint32_t qb = pair_base + buf * STG;
            int it = tid & 63;
            #pragma unroll
            for (int rep = 0; rep < 8; ++rep, it += 64) {   // 512 items / 64 thr
                int row = it >> 4, ch = it & 15;
                uint32_t o = sw128((uint32_t)((ch >> 3) * 4096 + row * 128 + (ch & 7) * 16));
                CP_ASYNC16(qb + o, (const void*)(g_m_h + (size_t)(m0 + row) * DD + ch * 8));
            }
        };

        load_quarter(t_beg, t_beg & 1);
        CP_COMMIT();

        for (int t = t_beg; t < t_end; ++t) {
            CP_WAIT0();        // this warp's half of tile t landed
            BAR_PAIR(barid);   // partner's half landed; partner done with the
                               // buffer we are about to overwrite (read t-2)
            if (t + 1 < t_end) load_quarter(t + 1, (t + 1) & 1);
            CP_COMMIT();

            const uint32_t mh = pair_base + (t & 1) * STG;

            // ---- weights prefetch, pre-scaled by 1/sqrt(d) ----
            float wreg[4][4];
            {
                const float* wp = wbase + (size_t)t * BM;
                #pragma unroll
                for (int nf = 0; nf < 4; ++nf) {
                    float2 w0 = *(const float2*)(wp + nf * 8);
                    float2 w1 = *(const float2*)(wp + nf * 8 + (size_t)8 * MT);
                    wreg[nf][0] = w0.x * SCALE; wreg[nf][1] = w0.y * SCALE;
                    wreg[nf][2] = w1.x * SCALE; wreg[nf][3] = w1.y * SCALE;
                }
            }

            // ---- S = Qh . Mh^T (16x32 per warp), A from registers ----
            float sf[4][4];
            #pragma unroll
            for (int nf = 0; nf < 4; ++nf)
                #pragma unroll
                for (int e = 0; e < 4; ++e) sf[nf][e] = 0.f;

            #pragma unroll
            for (int k = 0; k < 8; ++k) {
                const int half = k >> 2;
                const int cb   = (k & 3) * 2;
                uint32_t Bh[8];
                #pragma unroll
                for (int nfb = 0; nfb < 4; nfb += 2) {
                    uint32_t bo = sw128((uint32_t)(half * 4096
                                        + (nfb * 8 + sb_row) * 128
                                        + (cb + sb_sel) * 16));
                    ldsm_x4(Bh + nfb * 2, mh + bo);
                }
                #pragma unroll
                for (int nf = 0; nf < 4; ++nf) mma_f16(sf[nf], Aq[k], Bh + nf * 2);
            }

            // ---- weights * S, exp, pack P to fp16 A-fragments ----
            uint32_t aPh[2][4];
            #pragma unroll
            for (int nf = 0; nf < 4; ++nf) {
                float p[4];
                #pragma unroll
                for (int e = 0; e < 4; ++e) p[e] = __expf(sf[nf][e] * wreg[nf][e]);
                rs0 += p[0] + p[1];
                rs1 += p[2] + p[3];
                const int kf = nf >> 1;
                const int hi = (nf & 1) * 2;
                aPh[kf][hi]     = pack_h2(p[0], p[1]);
                aPh[kf][hi + 1] = pack_h2(p[2], p[3]);
            }

            // ---- O += Ph . Mh, single pass ----
            #pragma unroll
            for (int kf = 0; kf < 2; ++kf) {
                const int jb = (kf * 16 + pv_row) * 128;
                #pragma unroll
                for (int nfg = 0; nfg < 16; nfg += 4) {
                    uint32_t Bh[8];
                    #pragma unroll
                    for (int nfb = 0; nfb < 4; nfb += 2) {
                        const int nf = nfg + nfb;
                        uint32_t bo = sw128((uint32_t)((nf >> 3) * 4096 + jb
                                            + ((nf & 7) + pv_sel) * 16));
                        ldsm_x4t(Bh + nfb * 2, mh + bo);
                    }
                    #pragma unroll
                    for (int nfb = 0; nfb < 4; ++nfb)
                        mma_f16(o_acc[nfg + nfb], aPh[kf], Bh + nfb * 2);
                }
            }
        }

        // ---- segment epilogue: reduce + write partial slabs ----
        rs0 += __shfl_xor_sync(0xffffffffu, rs0, 1);
        rs0 += __shfl_xor_sync(0xffffffffu, rs0, 2);
        rs1 += __shfl_xor_sync(0xffffffffu, rs1, 1);
        rs1 += __shfl_xor_sync(0xffffffffu, rs1, 2);
        if (tig == 0) {
            atomicAdd(&lsum[qrow0 + gid], rs0);
            atomicAdd(&lsum[qrow0 + gid + 8], rs1);
        }
        __syncthreads();

        float* sO = (float*)(smem + S_M);   // reuse Mem region: [32][128] fp32
        for (int i = tid; i < 32 * 128; i += THREADS) sO[i] = 0.f;
        __syncthreads();
        #pragma unroll
        for (int nf = 0; nf < 16; ++nf) {
            const int cbase = nf * 8 + tig * 2;
            const int r0 = qrow0 + gid;
            atomicAdd(&sO[r0 * 128 + cbase],           o_acc[nf][0]);
            atomicAdd(&sO[r0 * 128 + cbase + 1],       o_acc[nf][1]);
            atomicAdd(&sO[(r0 + 8) * 128 + cbase],     o_acc[nf][2]);
            atomicAdd(&sO[(r0 + 8) * 128 + cbase + 1], o_acc[nf][3]);
        }
        __syncthreads();

        for (int i = tid; i < 32 * 32; i += THREADS) {
            int r  = i >> 5;
            int c4 = (i & 31) * 4;
            float4 v = *(float4*)(&sO[r * 128 + c4]);
            *(float4*)(&g_out_part[slot][(size_t)(q0 + r) * DD + c4]) = v;
        }
        if (tid < 32) g_lsum_part[slot][q0 + tid] = lsum[tid];
        __syncthreads();   // done with sO/lsum before next segment
    }
}

// ---------------- combine: out = (p0+p1)/(l0+l1) ----------------
__global__ void combine_kernel(float* __restrict__ out) {
    int idx = blockIdx.x * blockDim.x + threadIdx.x;
    if (idx >= QT * (DD / 4)) return;
    int r  = idx >> 5;
    int c4 = (idx & 31) * 4;
    float inv = 1.0f / (g_lsum_part[0][r] + g_lsum_part[1][r]);
    float4 a = *(float4*)(&g_out_part[0][(size_t)r * DD + c4]);
    float4 b = *(float4*)(&g_out_part[1][(size_t)r * DD + c4]);
    float4 v;
    v.x = (a.x + b.x) * inv; v.y = (a.y + b.y) * inv;
    v.z = (a.z + b.z) * inv; v.w = (a.w + b.w) * inv;
    *(float4*)(&out[(size_t)r * DD + c4]) = v;
}

// ---------------- launch ----------------
extern "C" void kernel_launch(void* const* d_in, const int* in_sizes, int n_in,
                              void* d_out, int out_size)
{
    const float* query   = (const float*)d_in[0];
    const float* memory  = (const float*)d_in[1];
    const float* weights = (const float*)d_in[2];
    float* out = (float*)d_out;

    cudaFuncSetAttribute(attn_mma_kernel,
                         cudaFuncAttributeMaxDynamicSharedMemorySize, SMEM_TOTAL);

    prep_kernel<<<((QT + MT) * DD / 4 + 255) / 256, 256>>>(query, memory);
    attn_mma_kernel<<<NCTA, THREADS, SMEM_TOTAL>>>(weights);
    combine_kernel<<<(QT * (DD / 4) + 255) / 256, 256>>>(out);
}